// round 13
// baseline (speedup 1.0000x reference)
#include <cuda_runtime.h>
#include <cuda_fp16.h>
#include <cstdint>

// ---------------------------------------------------------------------------
// Problem constants
// ---------------------------------------------------------------------------
constexpr int B = 64;
constexpr int I = 512;
constexpr int T = 512;
constexpr int H = 1024;
constexpr float DECAY = 0.8f;

// ---------------------------------------------------------------------------
// Device scratch
// ---------------------------------------------------------------------------
__device__ __half g_Ax[(size_t)B * T * I];          // fp16(x^T)          (b,t,i)
__device__ __half g_Wh[(size_t)H * I];              // fp16 hi of W^T-0.5 (h,i)
__device__ __half g_Wl[(size_t)H * I];              // fp16 lo of W^T-0.5
__device__ float  g_part[(size_t)B * 8 * T];        // partial rowsums (64-i tiles)
__device__ float  g_csum[(size_t)B * T];            // 0.5 * sum_i x[b,i,t]
__device__ float  g_proj[(size_t)T * B * H];        // proj (t, b, h)
__device__ int    g_cnt[B];                         // per-b tile completion count

// ---------------------------------------------------------------------------
// PTX helpers
// ---------------------------------------------------------------------------
__device__ __forceinline__ uint32_t s2u(const void* p) {
    uint32_t a;
    asm("{ .reg .u64 t; cvta.to.shared.u64 t, %1; cvt.u32.u64 %0, t; }"
        : "=r"(a) : "l"(p));
    return a;
}
__device__ __forceinline__ void cp16(uint32_t dst, const void* src) {
    asm volatile("cp.async.cg.shared.global [%0], [%1], 16;" :: "r"(dst), "l"(src));
}
__device__ __forceinline__ void cp_commit() {
    asm volatile("cp.async.commit_group;" ::: "memory");
}
template <int N>
__device__ __forceinline__ void cp_wait() {
    asm volatile("cp.async.wait_group %0;" :: "n"(N) : "memory");
}
__device__ __forceinline__ void ldm_x4(uint32_t& r0, uint32_t& r1, uint32_t& r2,
                                       uint32_t& r3, uint32_t addr) {
    asm volatile("ldmatrix.sync.aligned.m8n8.x4.shared.b16 {%0,%1,%2,%3}, [%4];"
                 : "=r"(r0), "=r"(r1), "=r"(r2), "=r"(r3) : "r"(addr));
}
__device__ __forceinline__ void mma16816(float* d, const uint32_t* a,
                                         uint32_t b0, uint32_t b1) {
    asm volatile(
        "mma.sync.aligned.m16n8k16.row.col.f32.f16.f16.f32 "
        "{%0,%1,%2,%3}, {%4,%5,%6,%7}, {%8,%9}, {%0,%1,%2,%3};"
        : "+f"(d[0]), "+f"(d[1]), "+f"(d[2]), "+f"(d[3])
        : "r"(a[0]), "r"(a[1]), "r"(a[2]), "r"(a[3]), "r"(b0), "r"(b1));
}
// packed fp32 pair ops
__device__ __forceinline__ void fma2(uint64_t& d, uint64_t a, uint64_t b) {
    asm("fma.rn.f32x2 %0, %1, %2, %0;" : "+l"(d) : "l"(a), "l"(b));
}
__device__ __forceinline__ uint64_t pack2(float v) {
    uint64_t r; asm("mov.b64 %0, {%1, %1};" : "=l"(r) : "f"(v)); return r;
}
__device__ __forceinline__ void unpack2(uint64_t p, float& lo, float& hi) {
    asm("mov.b64 {%0, %1}, %2;" : "=f"(lo), "=f"(hi) : "l"(p));
}

// ---------------------------------------------------------------------------
// Kernel 1: transpose x (B,I,T) fp32 -> (B,T,I) fp16, + partial rowsums.
// 64-wide i tiles -> 128B/row uint4 stores.
// ---------------------------------------------------------------------------
__global__ __launch_bounds__(256)
void conv_x(const float* __restrict__ x) {
    __shared__ float tile[64][33];
    __shared__ float psum[8][32];
    const int b  = blockIdx.z;
    const int t0 = blockIdx.x * 32;
    const int i0 = blockIdx.y * 64;
    const int tx = threadIdx.x;      // 0..31
    const int ty = threadIdx.y;      // 0..7

    const float* src = x + ((size_t)b * I + i0) * T + t0;
#pragma unroll
    for (int k = 0; k < 8; ++k)
        tile[ty + k * 8][tx] = src[(size_t)(ty + k * 8) * T + tx];
    __syncthreads();

    {
        const int id  = ty * 32 + tx;
        const int r   = id >> 3;             // t row 0..31
        const int seg = id & 7;              // i segment 0..7
        float v[8];
#pragma unroll
        for (int j = 0; j < 8; ++j) v[j] = tile[seg * 8 + j][r];
        __half2 q0 = __floats2half2_rn(v[0], v[1]);
        __half2 q1 = __floats2half2_rn(v[2], v[3]);
        __half2 q2 = __floats2half2_rn(v[4], v[5]);
        __half2 q3 = __floats2half2_rn(v[6], v[7]);
        uint4 u;
        u.x = *reinterpret_cast<uint32_t*>(&q0);
        u.y = *reinterpret_cast<uint32_t*>(&q1);
        u.z = *reinterpret_cast<uint32_t*>(&q2);
        u.w = *reinterpret_cast<uint32_t*>(&q3);
        __half* dh = g_Ax + ((size_t)b * T + t0 + r) * I + i0 + seg * 8;
        *reinterpret_cast<uint4*>(dh) = u;
    }

    float s = 0.0f;
#pragma unroll
    for (int k = 0; k < 8; ++k) s += tile[ty * 8 + k][tx];
    psum[ty][tx] = s;
    __syncthreads();
    if (ty == 0) {
        float tot = 0.0f;
#pragma unroll
        for (int j = 0; j < 8; ++j) tot += psum[j][tx];
        g_part[((size_t)b * 8 + blockIdx.y) * T + t0 + tx] = tot;
    }
}

// ---------------------------------------------------------------------------
// reduce partials -> g_csum; zero g_cnt each iteration.
// ---------------------------------------------------------------------------
__global__ __launch_bounds__(256)
void reduce_csum() {
    const int gid = blockIdx.x * blockDim.x + threadIdx.x;
    if (gid < B) g_cnt[gid] = 0;
    const int b = gid >> 9;
    const int t = gid & (T - 1);
    float s = 0.0f;
#pragma unroll
    for (int it = 0; it < 8; ++it)
        s += g_part[((size_t)b * 8 + it) * T + t];
    g_csum[(size_t)b * T + t] = 0.5f * s;
}

// ---------------------------------------------------------------------------
// Kernel 2: transpose W (I,H) fp32 -> (H,I), W-0.5 split into fp16 hi/lo
// ---------------------------------------------------------------------------
__global__ __launch_bounds__(256)
void conv_w(const float* __restrict__ W) {
    __shared__ float tile[32][33];
    const int h0 = blockIdx.x * 32;
    const int i0 = blockIdx.y * 32;
    const int tx = threadIdx.x;
    const int ty = threadIdx.y;

    const float* src = W + ((size_t)i0) * H + h0;
#pragma unroll
    for (int k = 0; k < 4; ++k)
        tile[ty + k * 8][tx] = src[(size_t)(ty + k * 8) * H + tx];
    __syncthreads();

    __half* dh = g_Wh + ((size_t)h0) * I + i0;
    __half* dl = g_Wl + ((size_t)h0) * I + i0;
#pragma unroll
    for (int k = 0; k < 4; ++k) {
        const int r = ty + k * 8;
        const float v = tile[tx][r] - 0.5f;
        const __half hi = __float2half(v);
        const __half lo = __float2half(v - __half2float(hi));
        dh[(size_t)r * I + tx] = hi;
        dl[(size_t)r * I + tx] = lo;
    }
}

// ---------------------------------------------------------------------------
// Kernel 3: fused hybrid GEMM + in-slot scan (grid = 2048, no extra CTAs).
//   Tile roles as round 11: 2/8 fp32 (h<256), 6/8 mma 2-product (h>=256).
//   SCANNERS: the mma CTAs with tb==3 && hb<4 (4 per batch b, the last bids
//   of b's range). After their tile: signal -> spin g_cnt[b]==32 -> scan
//   h-part [256*hb, 256*hb+256) -> write out. No extra resident CTAs, spins
//   are intra-wave (all awaited tiles have bids <= scanner's bid).
// ---------------------------------------------------------------------------
constexpr int BM = 128, BN = 128;

// mma-path config: 16 kc chunks, 3-stage (A,Bh,Bl) pipeline
constexpr int KC = 32;
constexpr int STAGES = 3;
constexpr int NSTG = I / KC;                    // 16
constexpr int ROWE = KC + 8;
constexpr int ROWB = ROWE * 2;                  // 80 bytes
constexpr int TILE_BYTES  = BM * ROWB;          // 10240
constexpr int STAGE_BYTES = 3 * TILE_BYTES;     // 30720
constexpr int SMEM_DYN = STAGES * STAGE_BYTES;  // 92160

// fp32-path config
constexpr int FK = 16;
constexpr int FTM = 8, FTN = 8;
constexpr int F_TILE  = FK * BM * 4;            // 8192
constexpr int F_STAGE = 2 * F_TILE;             // 16384

__global__ __launch_bounds__(256, 2)
void gemm_hybrid(const float* __restrict__ x, const float* __restrict__ W,
                 const float* __restrict__ bias, float* __restrict__ out) {
    extern __shared__ __align__(128) char smem[];
    const int tid = threadIdx.x;
    const int bid = blockIdx.x;
    const int sub = bid & 7;
    const bool is_fp32 = sub < 2;

    int b_done, hb_keep = -1, tb_keep = -1;

    if (is_fp32) {
        // ---------------- fp32 SGEMM (f32x2 + cp.async), h0 in [0,256) -----
        const int q  = (bid >> 3) * 2 + sub;            // 0..511
        const int hb = q & 1;
        const int r  = q >> 1;
        const int tb = r & 3;
        const int b  = r >> 2;
        const int t0 = tb * BM;
        const int h0 = hb * BN;
        b_done = b;

        const uint32_t sb = s2u(smem);
        const float* Ab = x + (size_t)b * I * T + t0;
        const float* Bb = W + h0;

        const int rf = tid >> 5;
        const int cf = tid & 31;

        auto load_stage = [&](int kt) {
            const uint32_t sA = sb + (kt & 3) * F_STAGE;
            const uint32_t sB = sA + F_TILE;
            const float* Ap = Ab + (size_t)kt * FK * T;
            const float* Bp = Bb + (size_t)kt * FK * H;
            cp16(sA + rf * 512 + cf * 16,       Ap + (size_t)rf * T + cf * 4);
            cp16(sA + (rf + 8) * 512 + cf * 16, Ap + (size_t)(rf + 8) * T + cf * 4);
            cp16(sB + rf * 512 + cf * 16,       Bp + (size_t)rf * H + cf * 4);
            cp16(sB + (rf + 8) * 512 + cf * 16, Bp + (size_t)(rf + 8) * H + cf * 4);
        };

        load_stage(0); cp_commit();
        load_stage(1); cp_commit();
        load_stage(2); cp_commit();

        const int tx  = tid & 15;
        const int ty  = tid >> 4;
        const int tm0 = ty * FTM;
        const int tn0 = tx * FTN;

        uint64_t acc2[FTM][FTN / 2];
#pragma unroll
        for (int i = 0; i < FTM; ++i)
#pragma unroll
            for (int j = 0; j < FTN / 2; ++j) acc2[i][j] = 0ull;

        constexpr int KT = I / FK;                      // 32
        for (int kt = 0; kt < KT; ++kt) {
            cp_wait<2>();
            __syncthreads();
            if (kt + 3 < KT) load_stage(kt + 3);
            cp_commit();

            const float* As = (const float*)(smem + (kt & 3) * F_STAGE);
            const float* Bs = (const float*)(smem + (kt & 3) * F_STAGE + F_TILE);
#pragma unroll
            for (int kk = 0; kk < FK; ++kk) {
                float a[FTM];
                uint64_t bb2[FTN / 2];
                *(float4*)&a[0] = *(const float4*)&As[kk * BM + tm0];
                *(float4*)&a[4] = *(const float4*)&As[kk * BM + tm0 + 4];
                *(ulonglong2*)&bb2[0] = *(const ulonglong2*)&Bs[kk * BN + tn0];
                *(ulonglong2*)&bb2[2] = *(const ulonglong2*)&Bs[kk * BN + tn0 + 4];
#pragma unroll
                for (int i = 0; i < FTM; ++i) {
                    const uint64_t aa = pack2(a[i]);
#pragma unroll
                    for (int j = 0; j < FTN / 2; ++j)
                        fma2(acc2[i][j], aa, bb2[j]);
                }
            }
        }

#pragma unroll
        for (int i = 0; i < FTM; ++i) {
            const int t = t0 + tm0 + i;
            float v[FTN];
#pragma unroll
            for (int j = 0; j < FTN / 2; ++j)
                unpack2(acc2[i][j], v[2 * j], v[2 * j + 1]);
            float* o = g_proj + ((size_t)t * B + b) * H + h0 + tn0;
            *(float4*)(o)     = make_float4(v[0], v[1], v[2], v[3]);
            *(float4*)(o + 4) = make_float4(v[4], v[5], v[6], v[7]);
        }
    } else {
        // -------- fp16 2-product MMA (A-dedup), h0 in [256,1024) --------
        const int q  = (bid >> 3) * 6 + (sub - 2);      // 0..1535
        const int hb = q % 6;
        const int r  = q / 6;
        const int tb = r & 3;
        const int b  = r >> 2;
        const int t0 = tb * BM;
        const int h0 = 256 + hb * BN;
        b_done = b; hb_keep = hb; tb_keep = tb;

        const uint32_t sb = s2u(smem);
        const int warp = tid >> 5;
        const int lane = tid & 31;
        const int wm = warp & 1;
        const int wn = warp >> 1;

        const int r0 = tid >> 1;
        const int c0 = (tid * 2) & 3;
        const int c1 = c0 + 1;

        const __half* Abase = g_Ax + ((size_t)(b * T + t0)) * I;
        const __half* Bhb = g_Wh + ((size_t)h0) * I;
        const __half* Blb = g_Wl + ((size_t)h0) * I;

        auto load_stage = [&](int kc) {
            const size_t i0 = (size_t)kc * KC;
            const uint32_t sA  = sb + (kc % STAGES) * STAGE_BYTES;
            const uint32_t sBh = sA + TILE_BYTES;
            const uint32_t sBl = sBh + TILE_BYTES;
            const __half* Ap  = Abase + i0;
            const __half* Bhp = Bhb + i0;
            const __half* Blp = Blb + i0;
            cp16(sA  + r0 * ROWB + c0 * 16, Ap  + (size_t)r0 * I + c0 * 8);
            cp16(sA  + r0 * ROWB + c1 * 16, Ap  + (size_t)r0 * I + c1 * 8);
            cp16(sBh + r0 * ROWB + c0 * 16, Bhp + (size_t)r0 * I + c0 * 8);
            cp16(sBh + r0 * ROWB + c1 * 16, Bhp + (size_t)r0 * I + c1 * 8);
            cp16(sBl + r0 * ROWB + c0 * 16, Blp + (size_t)r0 * I + c0 * 8);
            cp16(sBl + r0 * ROWB + c1 * 16, Blp + (size_t)r0 * I + c1 * 8);
        };

        load_stage(0); cp_commit();
        load_stage(1); cp_commit();

        float acc[4][4][4];
#pragma unroll
        for (int mt = 0; mt < 4; ++mt)
#pragma unroll
            for (int nj = 0; nj < 4; ++nj)
#pragma unroll
                for (int rr = 0; rr < 4; ++rr) acc[mt][nj][rr] = 0.0f;

        const int a_row = (lane & 15);
        const int a_kh  = (lane >> 4) * 8;
        const int b_row = (lane & 7) + ((lane >> 4) << 3);
        const int b_kh  = ((lane >> 3) & 1) * 8;

        for (int s = 0; s < NSTG; ++s) {
            cp_wait<STAGES - 2>();
            __syncthreads();
            if (s + STAGES - 1 < NSTG) load_stage(s + STAGES - 1);
            cp_commit();

            const uint32_t sA  = sb + (s % STAGES) * STAGE_BYTES;
            const uint32_t sBh = sA + TILE_BYTES;
            const uint32_t sBl = sBh + TILE_BYTES;

#pragma unroll
            for (int kk = 0; kk < KC; kk += 16) {
                uint32_t a[4][4], bb[2][4];
#pragma unroll
                for (int mt = 0; mt < 4; ++mt) {
                    const int m = wm * 64 + mt * 16 + a_row;
                    ldm_x4(a[mt][0], a[mt][1], a[mt][2], a[mt][3],
                           sA + m * ROWB + (kk + a_kh) * 2);
                }
#pragma unroll
                for (int nt = 0; nt < 2; ++nt) {
                    const int n = wn * 32 + nt * 16 + b_row;
                    ldm_x4(bb[nt][0], bb[nt][1], bb[nt][2], bb[nt][3],
                           sBh + n * ROWB + (kk + b_kh) * 2);
                }
#pragma unroll
                for (int mt = 0; mt < 4; ++mt)
#pragma unroll
                    for (int nj = 0; nj < 4; ++nj) {
                        const int nt = nj >> 1;
                        const int hh = (nj & 1) * 2;
                        mma16816(acc[mt][nj], a[mt], bb[nt][hh], bb[nt][hh + 1]);
                    }
#pragma unroll
                for (int nt = 0; nt < 2; ++nt) {
                    const int n = wn * 32 + nt * 16 + b_row;
                    ldm_x4(bb[nt][0], bb[nt][1], bb[nt][2], bb[nt][3],
                           sBl + n * ROWB + (kk + b_kh) * 2);
                }
#pragma unroll
                for (int mt = 0; mt < 4; ++mt)
#pragma unroll
                    for (int nj = 0; nj < 4; ++nj) {
                        const int nt = nj >> 1;
                        const int hh = (nj & 1) * 2;
                        mma16816(acc[mt][nj], a[mt], bb[nt][hh], bb[nt][hh + 1]);
                    }
            }
        }

#pragma unroll
        for (int mt = 0; mt < 4; ++mt) {
            const int tg = t0 + wm * 64 + mt * 16 + (lane >> 2);
            const float cc0 = g_csum[(size_t)b * T + tg];
            const float cc1 = g_csum[(size_t)b * T + tg + 8];
#pragma unroll
            for (int nj = 0; nj < 4; ++nj) {
                const int h = h0 + wn * 32 + nj * 8 + (lane & 3) * 2;
                float* o0 = g_proj + ((size_t)tg * B + b) * H + h;
                float* o1 = g_proj + ((size_t)(tg + 8) * B + b) * H + h;
                *(float2*)o0 = make_float2(acc[mt][nj][0] + cc0, acc[mt][nj][1] + cc0);
                *(float2*)o1 = make_float2(acc[mt][nj][2] + cc1, acc[mt][nj][3] + cc1);
            }
        }
    }

    // Tile completion signal.
    __syncthreads();
    if (tid == 0) {
        __threadfence();
        atomicAdd(&g_cnt[b_done], 1);
    }

    // ---------------- in-slot scan (4 scanner CTAs per batch) --------------
    if (tb_keep == 3 && hb_keep < 4) {
        const int b = b_done;
        if (tid == 0) {
            for (;;) {
                int v;
                asm volatile("ld.global.cg.s32 %0, [%1];" : "=r"(v)
                             : "l"(&g_cnt[b]));
                if (v >= 32) break;
                __nanosleep(256);
            }
        }
        __syncthreads();
        __threadfence();

        const int h = hb_keep * 256 + tid;
        const float bv = __ldg(bias + h);
        const float* p = g_proj + (size_t)b * H + h;
        constexpr int STRIDE = B * H;
        constexpr int CH = 16;

        float hc = 0.0f, y = 0.0f;
        float b0[CH], b1[CH];
#pragma unroll
        for (int j = 0; j < CH; ++j) b0[j] = p[(size_t)j * STRIDE];
#pragma unroll
        for (int j = 0; j < CH; ++j) b1[j] = p[(size_t)(CH + j) * STRIDE];

        for (int tt = 0; tt < T; tt += CH) {
            float b2[CH];
            if (tt + 2 * CH < T) {
                const float* pn = p + (size_t)(tt + 2 * CH) * STRIDE;
#pragma unroll
                for (int j = 0; j < CH; ++j) b2[j] = pn[(size_t)j * STRIDE];
            } else {
#pragma unroll
                for (int j = 0; j < CH; ++j) b2[j] = 0.0f;
            }
#pragma unroll
            for (int j = 0; j < CH; ++j) {
                hc = fmaxf(b0[j] + DECAY * hc * (1.0f - y), 0.0f);
                const float z = hc + bv;
                y = (z > 1.0f) ? z : 0.0f;
            }
#pragma unroll
            for (int j = 0; j < CH; ++j) b0[j] = b1[j];
#pragma unroll
            for (int j = 0; j < CH; ++j) b1[j] = b2[j];
        }
        out[(size_t)b * H + h] = y;
    }
}

// ---------------------------------------------------------------------------
extern "C" void kernel_launch(void* const* d_in, const int* in_sizes, int n_in,
                              void* d_out, int out_size) {
    const float* x    = (const float*)d_in[0];  // (B, I, T)
    const float* W    = (const float*)d_in[1];  // (I, H)
    const float* bias = (const float*)d_in[2];  // (1, H)
    float* out        = (float*)d_out;          // (B, H)

    cudaFuncSetAttribute(gemm_hybrid, cudaFuncAttributeMaxDynamicSharedMemorySize,
                         SMEM_DYN);

    conv_x<<<dim3(T / 32, I / 64, B), dim3(32, 8)>>>(x);
    reduce_csum<<<(B * T) / 256, 256>>>();
    conv_w<<<dim3(H / 32, I / 32), dim3(32, 8)>>>(W);
    gemm_hybrid<<<2048, 256, SMEM_DYN>>>(x, W, bias, out);
}

// round 14
// speedup vs baseline: 1.1102x; 1.1102x over previous
#include <cuda_runtime.h>
#include <cuda_fp16.h>
#include <cstdint>

// ---------------------------------------------------------------------------
// Problem constants
// ---------------------------------------------------------------------------
constexpr int B = 64;
constexpr int I = 512;
constexpr int T = 512;
constexpr int H = 1024;
constexpr float DECAY = 0.8f;

// ---------------------------------------------------------------------------
// Device scratch
// ---------------------------------------------------------------------------
__device__ __half g_Ax[(size_t)B * T * I];          // fp16(x^T)          (b,t,i)
__device__ __half g_Wh[(size_t)H * I];              // fp16 hi of W^T-0.5 (h,i)
__device__ __half g_Wl[(size_t)H * I];              // fp16 lo of W^T-0.5
__device__ float  g_part[(size_t)B * 8 * T];        // partial rowsums (64-i tiles)
__device__ float  g_csum[(size_t)B * T];            // 0.5 * sum_i x[b,i,t]
__device__ float  g_proj[(size_t)B * T * H];        // proj (b, t, h)  <- scan-friendly
__device__ int    g_cnt[B];                         // per-b tile completion count

// ---------------------------------------------------------------------------
// PTX helpers
// ---------------------------------------------------------------------------
__device__ __forceinline__ uint32_t s2u(const void* p) {
    uint32_t a;
    asm("{ .reg .u64 t; cvta.to.shared.u64 t, %1; cvt.u32.u64 %0, t; }"
        : "=r"(a) : "l"(p));
    return a;
}
__device__ __forceinline__ void cp16(uint32_t dst, const void* src) {
    asm volatile("cp.async.cg.shared.global [%0], [%1], 16;" :: "r"(dst), "l"(src));
}
__device__ __forceinline__ void cp_commit() {
    asm volatile("cp.async.commit_group;" ::: "memory");
}
template <int N>
__device__ __forceinline__ void cp_wait() {
    asm volatile("cp.async.wait_group %0;" :: "n"(N) : "memory");
}
__device__ __forceinline__ void ldm_x4(uint32_t& r0, uint32_t& r1, uint32_t& r2,
                                       uint32_t& r3, uint32_t addr) {
    asm volatile("ldmatrix.sync.aligned.m8n8.x4.shared.b16 {%0,%1,%2,%3}, [%4];"
                 : "=r"(r0), "=r"(r1), "=r"(r2), "=r"(r3) : "r"(addr));
}
__device__ __forceinline__ void mma16816(float* d, const uint32_t* a,
                                         uint32_t b0, uint32_t b1) {
    asm volatile(
        "mma.sync.aligned.m16n8k16.row.col.f32.f16.f16.f32 "
        "{%0,%1,%2,%3}, {%4,%5,%6,%7}, {%8,%9}, {%0,%1,%2,%3};"
        : "+f"(d[0]), "+f"(d[1]), "+f"(d[2]), "+f"(d[3])
        : "r"(a[0]), "r"(a[1]), "r"(a[2]), "r"(a[3]), "r"(b0), "r"(b1));
}
// packed fp32 pair ops
__device__ __forceinline__ void fma2(uint64_t& d, uint64_t a, uint64_t b) {
    asm("fma.rn.f32x2 %0, %1, %2, %0;" : "+l"(d) : "l"(a), "l"(b));
}
__device__ __forceinline__ uint64_t pack2(float v) {
    uint64_t r; asm("mov.b64 %0, {%1, %1};" : "=l"(r) : "f"(v)); return r;
}
__device__ __forceinline__ void unpack2(uint64_t p, float& lo, float& hi) {
    asm("mov.b64 {%0, %1}, %2;" : "=f"(lo), "=f"(hi) : "l"(p));
}

// ---------------------------------------------------------------------------
// Kernel 1: transpose x (B,I,T) fp32 -> (B,T,I) fp16, + partial rowsums.
// ---------------------------------------------------------------------------
__global__ __launch_bounds__(256)
void conv_x(const float* __restrict__ x) {
    __shared__ float tile[64][33];
    __shared__ float psum[8][32];
    const int b  = blockIdx.z;
    const int t0 = blockIdx.x * 32;
    const int i0 = blockIdx.y * 64;
    const int tx = threadIdx.x;      // 0..31
    const int ty = threadIdx.y;      // 0..7

    const float* src = x + ((size_t)b * I + i0) * T + t0;
#pragma unroll
    for (int k = 0; k < 8; ++k)
        tile[ty + k * 8][tx] = src[(size_t)(ty + k * 8) * T + tx];
    __syncthreads();

    {
        const int id  = ty * 32 + tx;
        const int r   = id >> 3;             // t row 0..31
        const int seg = id & 7;              // i segment 0..7
        float v[8];
#pragma unroll
        for (int j = 0; j < 8; ++j) v[j] = tile[seg * 8 + j][r];
        __half2 q0 = __floats2half2_rn(v[0], v[1]);
        __half2 q1 = __floats2half2_rn(v[2], v[3]);
        __half2 q2 = __floats2half2_rn(v[4], v[5]);
        __half2 q3 = __floats2half2_rn(v[6], v[7]);
        uint4 u;
        u.x = *reinterpret_cast<uint32_t*>(&q0);
        u.y = *reinterpret_cast<uint32_t*>(&q1);
        u.z = *reinterpret_cast<uint32_t*>(&q2);
        u.w = *reinterpret_cast<uint32_t*>(&q3);
        __half* dh = g_Ax + ((size_t)b * T + t0 + r) * I + i0 + seg * 8;
        *reinterpret_cast<uint4*>(dh) = u;
    }

    float s = 0.0f;
#pragma unroll
    for (int k = 0; k < 8; ++k) s += tile[ty * 8 + k][tx];
    psum[ty][tx] = s;
    __syncthreads();
    if (ty == 0) {
        float tot = 0.0f;
#pragma unroll
        for (int j = 0; j < 8; ++j) tot += psum[j][tx];
        g_part[((size_t)b * 8 + blockIdx.y) * T + t0 + tx] = tot;
    }
}

// ---------------------------------------------------------------------------
// Kernel 2 (merged): conv_w (bid<512) + reduce_csum/zero-cnt (bid>=512).
// Both depend only on conv_x (stream order); merging saves a launch gap.
// ---------------------------------------------------------------------------
__global__ __launch_bounds__(256)
void conv_w_reduce(const float* __restrict__ W) {
    const int bid = blockIdx.x;
    if (bid < 512) {
        // conv_w role: 32x32 W transpose+split tile
        __shared__ float tile[32][33];
        const int h0 = (bid & 31) * 32;
        const int i0 = (bid >> 5) * 32;
        const int tx = threadIdx.x & 31;
        const int ty = threadIdx.x >> 5;

        const float* src = W + ((size_t)i0) * H + h0;
#pragma unroll
        for (int k = 0; k < 4; ++k)
            tile[ty + k * 8][tx] = src[(size_t)(ty + k * 8) * H + tx];
        __syncthreads();

        __half* dh = g_Wh + ((size_t)h0) * I + i0;
        __half* dl = g_Wl + ((size_t)h0) * I + i0;
#pragma unroll
        for (int k = 0; k < 4; ++k) {
            const int r = ty + k * 8;
            const float v = tile[tx][r] - 0.5f;
            const __half hi = __float2half(v);
            const __half lo = __float2half(v - __half2float(hi));
            dh[(size_t)r * I + tx] = hi;
            dl[(size_t)r * I + tx] = lo;
        }
    } else {
        // reduce role
        const int gid = (bid - 512) * 256 + threadIdx.x;   // 0 .. B*T-1
        if (gid < B) g_cnt[gid] = 0;
        const int b = gid >> 9;
        const int t = gid & (T - 1);
        float s = 0.0f;
#pragma unroll
        for (int it = 0; it < 8; ++it)
            s += g_part[((size_t)b * 8 + it) * T + t];
        g_csum[(size_t)b * T + t] = 0.5f * s;
    }
}

// ---------------------------------------------------------------------------
// Kernel 3: fused hybrid GEMM + tail scan (round-12 structure, best known).
//   bid in [0,2048):    GEMM tiles (2/8 fp32 h<256, 6/8 mma 2-product).
//   bid in [2048,2304): scan CTAs (tail wave), spin g_cnt[b]==32 then scan.
// proj is (b,t,h): scan t-stride = 4KB (page-local), writes equally coalesced.
// ---------------------------------------------------------------------------
constexpr int BM = 128, BN = 128;

constexpr int KC = 32;
constexpr int STAGES = 3;
constexpr int NSTG = I / KC;                    // 16
constexpr int ROWE = KC + 8;
constexpr int ROWB = ROWE * 2;                  // 80 bytes
constexpr int TILE_BYTES  = BM * ROWB;          // 10240
constexpr int STAGE_BYTES = 3 * TILE_BYTES;     // 30720
constexpr int SMEM_DYN = STAGES * STAGE_BYTES;  // 92160

constexpr int FK = 16;
constexpr int FTM = 8, FTN = 8;
constexpr int F_TILE  = FK * BM * 4;            // 8192
constexpr int F_STAGE = 2 * F_TILE;             // 16384

__global__ __launch_bounds__(256, 2)
void gemm_hybrid(const float* __restrict__ x, const float* __restrict__ W,
                 const float* __restrict__ bias, float* __restrict__ out) {
    extern __shared__ __align__(128) char smem[];
    const int tid = threadIdx.x;
    const int bid = blockIdx.x;

    if (bid >= 2048) {
        // ================= scan role (tail) =================
        const int g    = bid - 2048;            // 0..255
        const int b    = g >> 2;
        const int part = g & 3;
        const int h    = part * 256 + tid;

        if (tid == 0) {
            for (;;) {
                int v;
                asm volatile("ld.global.cg.s32 %0, [%1];" : "=r"(v)
                             : "l"(&g_cnt[b]));
                if (v >= 32) break;
                __nanosleep(512);
            }
        }
        __syncthreads();
        __threadfence();

        const float bv = __ldg(bias + h);
        const float* p = g_proj + ((size_t)b * T) * H + h;
        constexpr int STRIDE = H;                // 4KB t-stride
        constexpr int CH = 16;

        float hc = 0.0f, y = 0.0f;
        float b0[CH], b1[CH];
#pragma unroll
        for (int j = 0; j < CH; ++j) b0[j] = p[(size_t)j * STRIDE];
#pragma unroll
        for (int j = 0; j < CH; ++j) b1[j] = p[(size_t)(CH + j) * STRIDE];

        for (int tt = 0; tt < T; tt += CH) {
            float b2[CH];
            if (tt + 2 * CH < T) {
                const float* pn = p + (size_t)(tt + 2 * CH) * STRIDE;
#pragma unroll
                for (int j = 0; j < CH; ++j) b2[j] = pn[(size_t)j * STRIDE];
            } else {
#pragma unroll
                for (int j = 0; j < CH; ++j) b2[j] = 0.0f;
            }
#pragma unroll
            for (int j = 0; j < CH; ++j) {
                hc = fmaxf(b0[j] + DECAY * hc * (1.0f - y), 0.0f);
                const float z = hc + bv;
                y = (z > 1.0f) ? z : 0.0f;
            }
#pragma unroll
            for (int j = 0; j < CH; ++j) b0[j] = b1[j];
#pragma unroll
            for (int j = 0; j < CH; ++j) b1[j] = b2[j];
        }
        out[(size_t)b * H + h] = y;
        return;
    }

    const int sub = bid & 7;
    const bool is_fp32 = sub < 2;
    int b_done;

    if (is_fp32) {
        // ---------------- fp32 SGEMM (f32x2 + cp.async), h0 in [0,256) -----
        const int q  = (bid >> 3) * 2 + sub;            // 0..511
        const int hb = q & 1;
        const int r  = q >> 1;
        const int tb = r & 3;
        const int b  = r >> 2;
        const int t0 = tb * BM;
        const int h0 = hb * BN;
        b_done = b;

        const uint32_t sb = s2u(smem);
        const float* Ab = x + (size_t)b * I * T + t0;
        const float* Bb = W + h0;

        const int rf = tid >> 5;
        const int cf = tid & 31;

        auto load_stage = [&](int kt) {
            const uint32_t sA = sb + (kt & 3) * F_STAGE;
            const uint32_t sB = sA + F_TILE;
            const float* Ap = Ab + (size_t)kt * FK * T;
            const float* Bp = Bb + (size_t)kt * FK * H;
            cp16(sA + rf * 512 + cf * 16,       Ap + (size_t)rf * T + cf * 4);
            cp16(sA + (rf + 8) * 512 + cf * 16, Ap + (size_t)(rf + 8) * T + cf * 4);
            cp16(sB + rf * 512 + cf * 16,       Bp + (size_t)rf * H + cf * 4);
            cp16(sB + (rf + 8) * 512 + cf * 16, Bp + (size_t)(rf + 8) * H + cf * 4);
        };

        load_stage(0); cp_commit();
        load_stage(1); cp_commit();
        load_stage(2); cp_commit();

        const int tx  = tid & 15;
        const int ty  = tid >> 4;
        const int tm0 = ty * FTM;
        const int tn0 = tx * FTN;

        uint64_t acc2[FTM][FTN / 2];
#pragma unroll
        for (int i = 0; i < FTM; ++i)
#pragma unroll
            for (int j = 0; j < FTN / 2; ++j) acc2[i][j] = 0ull;

        constexpr int KT = I / FK;                      // 32
        for (int kt = 0; kt < KT; ++kt) {
            cp_wait<2>();
            __syncthreads();
            if (kt + 3 < KT) load_stage(kt + 3);
            cp_commit();

            const float* As = (const float*)(smem + (kt & 3) * F_STAGE);
            const float* Bs = (const float*)(smem + (kt & 3) * F_STAGE + F_TILE);
#pragma unroll
            for (int kk = 0; kk < FK; ++kk) {
                float a[FTM];
                uint64_t bb2[FTN / 2];
                *(float4*)&a[0] = *(const float4*)&As[kk * BM + tm0];
                *(float4*)&a[4] = *(const float4*)&As[kk * BM + tm0 + 4];
                *(ulonglong2*)&bb2[0] = *(const ulonglong2*)&Bs[kk * BN + tn0];
                *(ulonglong2*)&bb2[2] = *(const ulonglong2*)&Bs[kk * BN + tn0 + 4];
#pragma unroll
                for (int i = 0; i < FTM; ++i) {
                    const uint64_t aa = pack2(a[i]);
#pragma unroll
                    for (int j = 0; j < FTN / 2; ++j)
                        fma2(acc2[i][j], aa, bb2[j]);
                }
            }
        }

#pragma unroll
        for (int i = 0; i < FTM; ++i) {
            const int t = t0 + tm0 + i;
            float v[FTN];
#pragma unroll
            for (int j = 0; j < FTN / 2; ++j)
                unpack2(acc2[i][j], v[2 * j], v[2 * j + 1]);
            float* o = g_proj + ((size_t)b * T + t) * H + h0 + tn0;
            *(float4*)(o)     = make_float4(v[0], v[1], v[2], v[3]);
            *(float4*)(o + 4) = make_float4(v[4], v[5], v[6], v[7]);
        }
    } else {
        // -------- fp16 2-product MMA (A-dedup), h0 in [256,1024) --------
        const int q  = (bid >> 3) * 6 + (sub - 2);      // 0..1535
        const int hb = q % 6;
        const int r  = q / 6;
        const int tb = r & 3;
        const int b  = r >> 2;
        const int t0 = tb * BM;
        const int h0 = 256 + hb * BN;
        b_done = b;

        const uint32_t sb = s2u(smem);
        const int warp = tid >> 5;
        const int lane = tid & 31;
        const int wm = warp & 1;
        const int wn = warp >> 1;

        const int r0 = tid >> 1;
        const int c0 = (tid * 2) & 3;
        const int c1 = c0 + 1;

        const __half* Abase = g_Ax + ((size_t)(b * T + t0)) * I;
        const __half* Bhb = g_Wh + ((size_t)h0) * I;
        const __half* Blb = g_Wl + ((size_t)h0) * I;

        auto load_stage = [&](int kc) {
            const size_t i0 = (size_t)kc * KC;
            const uint32_t sA  = sb + (kc % STAGES) * STAGE_BYTES;
            const uint32_t sBh = sA + TILE_BYTES;
            const uint32_t sBl = sBh + TILE_BYTES;
            const __half* Ap  = Abase + i0;
            const __half* Bhp = Bhb + i0;
            const __half* Blp = Blb + i0;
            cp16(sA  + r0 * ROWB + c0 * 16, Ap  + (size_t)r0 * I + c0 * 8);
            cp16(sA  + r0 * ROWB + c1 * 16, Ap  + (size_t)r0 * I + c1 * 8);
            cp16(sBh + r0 * ROWB + c0 * 16, Bhp + (size_t)r0 * I + c0 * 8);
            cp16(sBh + r0 * ROWB + c1 * 16, Bhp + (size_t)r0 * I + c1 * 8);
            cp16(sBl + r0 * ROWB + c0 * 16, Blp + (size_t)r0 * I + c0 * 8);
            cp16(sBl + r0 * ROWB + c1 * 16, Blp + (size_t)r0 * I + c1 * 8);
        };

        load_stage(0); cp_commit();
        load_stage(1); cp_commit();

        float acc[4][4][4];
#pragma unroll
        for (int mt = 0; mt < 4; ++mt)
#pragma unroll
            for (int nj = 0; nj < 4; ++nj)
#pragma unroll
                for (int rr = 0; rr < 4; ++rr) acc[mt][nj][rr] = 0.0f;

        const int a_row = (lane & 15);
        const int a_kh  = (lane >> 4) * 8;
        const int b_row = (lane & 7) + ((lane >> 4) << 3);
        const int b_kh  = ((lane >> 3) & 1) * 8;

        for (int s = 0; s < NSTG; ++s) {
            cp_wait<STAGES - 2>();
            __syncthreads();
            if (s + STAGES - 1 < NSTG) load_stage(s + STAGES - 1);
            cp_commit();

            const uint32_t sA  = sb + (s % STAGES) * STAGE_BYTES;
            const uint32_t sBh = sA + TILE_BYTES;
            const uint32_t sBl = sBh + TILE_BYTES;

#pragma unroll
            for (int kk = 0; kk < KC; kk += 16) {
                uint32_t a[4][4], bb[2][4];
#pragma unroll
                for (int mt = 0; mt < 4; ++mt) {
                    const int m = wm * 64 + mt * 16 + a_row;
                    ldm_x4(a[mt][0], a[mt][1], a[mt][2], a[mt][3],
                           sA + m * ROWB + (kk + a_kh) * 2);
                }
#pragma unroll
                for (int nt = 0; nt < 2; ++nt) {
                    const int n = wn * 32 + nt * 16 + b_row;
                    ldm_x4(bb[nt][0], bb[nt][1], bb[nt][2], bb[nt][3],
                           sBh + n * ROWB + (kk + b_kh) * 2);
                }
#pragma unroll
                for (int mt = 0; mt < 4; ++mt)
#pragma unroll
                    for (int nj = 0; nj < 4; ++nj) {
                        const int nt = nj >> 1;
                        const int hh = (nj & 1) * 2;
                        mma16816(acc[mt][nj], a[mt], bb[nt][hh], bb[nt][hh + 1]);
                    }
#pragma unroll
                for (int nt = 0; nt < 2; ++nt) {
                    const int n = wn * 32 + nt * 16 + b_row;
                    ldm_x4(bb[nt][0], bb[nt][1], bb[nt][2], bb[nt][3],
                           sBl + n * ROWB + (kk + b_kh) * 2);
                }
#pragma unroll
                for (int mt = 0; mt < 4; ++mt)
#pragma unroll
                    for (int nj = 0; nj < 4; ++nj) {
                        const int nt = nj >> 1;
                        const int hh = (nj & 1) * 2;
                        mma16816(acc[mt][nj], a[mt], bb[nt][hh], bb[nt][hh + 1]);
                    }
            }
        }

#pragma unroll
        for (int mt = 0; mt < 4; ++mt) {
            const int tg = t0 + wm * 64 + mt * 16 + (lane >> 2);
            const float cc0 = g_csum[(size_t)b * T + tg];
            const float cc1 = g_csum[(size_t)b * T + tg + 8];
#pragma unroll
            for (int nj = 0; nj < 4; ++nj) {
                const int h = h0 + wn * 32 + nj * 8 + (lane & 3) * 2;
                float* o0 = g_proj + ((size_t)b * T + tg) * H + h;
                float* o1 = g_proj + ((size_t)b * T + tg + 8) * H + h;
                *(float2*)o0 = make_float2(acc[mt][nj][0] + cc0, acc[mt][nj][1] + cc0);
                *(float2*)o1 = make_float2(acc[mt][nj][2] + cc1, acc[mt][nj][3] + cc1);
            }
        }
    }

    // Tile completion signal.
    __syncthreads();
    if (tid == 0) {
        __threadfence();
        atomicAdd(&g_cnt[b_done], 1);
    }
}

// ---------------------------------------------------------------------------
extern "C" void kernel_launch(void* const* d_in, const int* in_sizes, int n_in,
                              void* d_out, int out_size) {
    const float* x    = (const float*)d_in[0];  // (B, I, T)
    const float* W    = (const float*)d_in[1];  // (I, H)
    const float* bias = (const float*)d_in[2];  // (1, H)
    float* out        = (float*)d_out;          // (B, H)

    cudaFuncSetAttribute(gemm_hybrid, cudaFuncAttributeMaxDynamicSharedMemorySize,
                         SMEM_DYN);

    conv_x<<<dim3(T / 32, I / 64, B), dim3(32, 8)>>>(x);
    conv_w_reduce<<<512 + (B * T) / 256, 256>>>(W);
    gemm_hybrid<<<2048 + 256, 256, SMEM_DYN>>>(x, W, bias, out);
}

// round 15
// speedup vs baseline: 1.1309x; 1.0187x over previous
#include <cuda_runtime.h>
#include <cuda_fp16.h>
#include <cstdint>

// ---------------------------------------------------------------------------
// Problem constants
// ---------------------------------------------------------------------------
constexpr int B = 64;
constexpr int I = 512;
constexpr int T = 512;
constexpr int H = 1024;
constexpr float DECAY = 0.8f;

// ---------------------------------------------------------------------------
// Device scratch
// ---------------------------------------------------------------------------
__device__ __half g_Ax[(size_t)B * T * I];          // fp16(x^T)          (b,t,i)
__device__ __half g_Wh[(size_t)H * I];              // fp16 hi of W^T-0.5 (h,i)
__device__ __half g_Wl[(size_t)H * I];              // fp16 lo of W^T-0.5
__device__ float  g_part[(size_t)B * 8 * T];        // partial rowsums (64-i tiles)
__device__ float  g_csum[(size_t)B * T];            // 0.5 * sum_i x[b,i,t]
__device__ float  g_proj[(size_t)B * T * H];        // proj (b, t, h)
__device__ int    g_cnt[B * 4];                     // per-(b,tb) completion count

// ---------------------------------------------------------------------------
// PTX helpers
// ---------------------------------------------------------------------------
__device__ __forceinline__ uint32_t s2u(const void* p) {
    uint32_t a;
    asm("{ .reg .u64 t; cvta.to.shared.u64 t, %1; cvt.u32.u64 %0, t; }"
        : "=r"(a) : "l"(p));
    return a;
}
__device__ __forceinline__ void cp16(uint32_t dst, const void* src) {
    asm volatile("cp.async.cg.shared.global [%0], [%1], 16;" :: "r"(dst), "l"(src));
}
__device__ __forceinline__ void cp_commit() {
    asm volatile("cp.async.commit_group;" ::: "memory");
}
template <int N>
__device__ __forceinline__ void cp_wait() {
    asm volatile("cp.async.wait_group %0;" :: "n"(N) : "memory");
}
__device__ __forceinline__ void ldm_x4(uint32_t& r0, uint32_t& r1, uint32_t& r2,
                                       uint32_t& r3, uint32_t addr) {
    asm volatile("ldmatrix.sync.aligned.m8n8.x4.shared.b16 {%0,%1,%2,%3}, [%4];"
                 : "=r"(r0), "=r"(r1), "=r"(r2), "=r"(r3) : "r"(addr));
}
__device__ __forceinline__ void mma16816(float* d, const uint32_t* a,
                                         uint32_t b0, uint32_t b1) {
    asm volatile(
        "mma.sync.aligned.m16n8k16.row.col.f32.f16.f16.f32 "
        "{%0,%1,%2,%3}, {%4,%5,%6,%7}, {%8,%9}, {%0,%1,%2,%3};"
        : "+f"(d[0]), "+f"(d[1]), "+f"(d[2]), "+f"(d[3])
        : "r"(a[0]), "r"(a[1]), "r"(a[2]), "r"(a[3]), "r"(b0), "r"(b1));
}
// packed fp32 pair ops
__device__ __forceinline__ void fma2(uint64_t& d, uint64_t a, uint64_t b) {
    asm("fma.rn.f32x2 %0, %1, %2, %0;" : "+l"(d) : "l"(a), "l"(b));
}
__device__ __forceinline__ uint64_t pack2(float v) {
    uint64_t r; asm("mov.b64 %0, {%1, %1};" : "=l"(r) : "f"(v)); return r;
}
__device__ __forceinline__ void unpack2(uint64_t p, float& lo, float& hi) {
    asm("mov.b64 {%0, %1}, %2;" : "=f"(lo), "=f"(hi) : "l"(p));
}

// ---------------------------------------------------------------------------
// Kernel 1: transpose x (B,I,T) fp32 -> (B,T,I) fp16, + partial rowsums.
// ---------------------------------------------------------------------------
__global__ __launch_bounds__(256)
void conv_x(const float* __restrict__ x) {
    __shared__ float tile[64][33];
    __shared__ float psum[8][32];
    const int b  = blockIdx.z;
    const int t0 = blockIdx.x * 32;
    const int i0 = blockIdx.y * 64;
    const int tx = threadIdx.x;      // 0..31
    const int ty = threadIdx.y;      // 0..7

    const float* src = x + ((size_t)b * I + i0) * T + t0;
#pragma unroll
    for (int k = 0; k < 8; ++k)
        tile[ty + k * 8][tx] = src[(size_t)(ty + k * 8) * T + tx];
    __syncthreads();

    {
        const int id  = ty * 32 + tx;
        const int r   = id >> 3;             // t row 0..31
        const int seg = id & 7;              // i segment 0..7
        float v[8];
#pragma unroll
        for (int j = 0; j < 8; ++j) v[j] = tile[seg * 8 + j][r];
        __half2 q0 = __floats2half2_rn(v[0], v[1]);
        __half2 q1 = __floats2half2_rn(v[2], v[3]);
        __half2 q2 = __floats2half2_rn(v[4], v[5]);
        __half2 q3 = __floats2half2_rn(v[6], v[7]);
        uint4 u;
        u.x = *reinterpret_cast<uint32_t*>(&q0);
        u.y = *reinterpret_cast<uint32_t*>(&q1);
        u.z = *reinterpret_cast<uint32_t*>(&q2);
        u.w = *reinterpret_cast<uint32_t*>(&q3);
        __half* dh = g_Ax + ((size_t)b * T + t0 + r) * I + i0 + seg * 8;
        *reinterpret_cast<uint4*>(dh) = u;
    }

    float s = 0.0f;
#pragma unroll
    for (int k = 0; k < 8; ++k) s += tile[ty * 8 + k][tx];
    psum[ty][tx] = s;
    __syncthreads();
    if (ty == 0) {
        float tot = 0.0f;
#pragma unroll
        for (int j = 0; j < 8; ++j) tot += psum[j][tx];
        g_part[((size_t)b * 8 + blockIdx.y) * T + t0 + tx] = tot;
    }
}

// ---------------------------------------------------------------------------
// Kernel 2 (merged): conv_w (bid<512) + reduce_csum/zero-cnt (bid>=512).
// ---------------------------------------------------------------------------
__global__ __launch_bounds__(256)
void conv_w_reduce(const float* __restrict__ W) {
    const int bid = blockIdx.x;
    if (bid < 512) {
        __shared__ float tile[32][33];
        const int h0 = (bid & 31) * 32;
        const int i0 = (bid >> 5) * 32;
        const int tx = threadIdx.x & 31;
        const int ty = threadIdx.x >> 5;

        const float* src = W + ((size_t)i0) * H + h0;
#pragma unroll
        for (int k = 0; k < 4; ++k)
            tile[ty + k * 8][tx] = src[(size_t)(ty + k * 8) * H + tx];
        __syncthreads();

        __half* dh = g_Wh + ((size_t)h0) * I + i0;
        __half* dl = g_Wl + ((size_t)h0) * I + i0;
#pragma unroll
        for (int k = 0; k < 4; ++k) {
            const int r = ty + k * 8;
            const float v = tile[tx][r] - 0.5f;
            const __half hi = __float2half(v);
            const __half lo = __float2half(v - __half2float(hi));
            dh[(size_t)r * I + tx] = hi;
            dl[(size_t)r * I + tx] = lo;
        }
    } else {
        const int gid = (bid - 512) * 256 + threadIdx.x;   // 0 .. B*T-1
        if (gid < B * 4) g_cnt[gid] = 0;
        const int b = gid >> 9;
        const int t = gid & (T - 1);
        float s = 0.0f;
#pragma unroll
        for (int it = 0; it < 8; ++it)
            s += g_part[((size_t)b * 8 + it) * T + t];
        g_csum[(size_t)b * T + t] = 0.5f * s;
    }
}

// ---------------------------------------------------------------------------
// Kernel 3: fused hybrid GEMM + pipelined tail scan.
//   bid in [0,2048):    GEMM tiles (2/8 fp32 h<256, 6/8 mma 2-product).
//     signal per-(b,tb): atomicAdd(g_cnt[b*4+tb]) after stores+fence.
//   bid in [2048,2304): scan CTAs. Consume proj quarter-by-quarter: spin
//     g_cnt[b*4+q]==8 just before the prefetch window enters quarter q.
//     -> scan tracks the GEMM per-tb instead of serializing after whole-b.
// ---------------------------------------------------------------------------
constexpr int BM = 128, BN = 128;

constexpr int KC = 32;
constexpr int STAGES = 3;
constexpr int NSTG = I / KC;                    // 16
constexpr int ROWE = KC + 8;
constexpr int ROWB = ROWE * 2;                  // 80 bytes
constexpr int TILE_BYTES  = BM * ROWB;          // 10240
constexpr int STAGE_BYTES = 3 * TILE_BYTES;     // 30720
constexpr int SMEM_DYN = STAGES * STAGE_BYTES;  // 92160

constexpr int FK = 16;
constexpr int FTM = 8, FTN = 8;
constexpr int F_TILE  = FK * BM * 4;            // 8192
constexpr int F_STAGE = 2 * F_TILE;             // 16384

__global__ __launch_bounds__(256, 2)
void gemm_hybrid(const float* __restrict__ x, const float* __restrict__ W,
                 const float* __restrict__ bias, float* __restrict__ out) {
    extern __shared__ __align__(128) char smem[];
    const int tid = threadIdx.x;
    const int bid = blockIdx.x;

    if (bid >= 2048) {
        // ================= scan role (quarter-pipelined) =================
        const int g    = bid - 2048;            // 0..255
        const int b    = g >> 2;
        const int part = g & 3;
        const int h    = part * 256 + tid;

        int q_done = -1;
        auto wait_quarter = [&](int q) {
            if (q > 3) q = 3;
            if (q <= q_done) return;
            if (tid == 0) {
                for (;;) {
                    int v;
                    asm volatile("ld.global.cg.s32 %0, [%1];" : "=r"(v)
                                 : "l"(&g_cnt[b * 4 + q]));
                    if (v >= 8) break;
                    __nanosleep(256);
                }
            }
            __syncthreads();
            __threadfence();
            q_done = q;
        };

        const float bv = __ldg(bias + h);
        const float* p = g_proj + ((size_t)b * T) * H + h;
        constexpr int STRIDE = H;                // 4KB t-stride
        constexpr int CH = 16;

        float hc = 0.0f, y = 0.0f;
        float b0[CH], b1[CH];
        wait_quarter(0);                         // t in [0,32)
#pragma unroll
        for (int j = 0; j < CH; ++j) b0[j] = p[(size_t)j * STRIDE];
#pragma unroll
        for (int j = 0; j < CH; ++j) b1[j] = p[(size_t)(CH + j) * STRIDE];

        for (int tt = 0; tt < T; tt += CH) {
            float b2[CH];
            if (tt + 2 * CH < T) {
                wait_quarter((tt + 3 * CH - 1) >> 7);   // prefetch max idx tt+47
                const float* pn = p + (size_t)(tt + 2 * CH) * STRIDE;
#pragma unroll
                for (int j = 0; j < CH; ++j) b2[j] = pn[(size_t)j * STRIDE];
            } else {
#pragma unroll
                for (int j = 0; j < CH; ++j) b2[j] = 0.0f;
            }
#pragma unroll
            for (int j = 0; j < CH; ++j) {
                hc = fmaxf(b0[j] + DECAY * hc * (1.0f - y), 0.0f);
                const float z = hc + bv;
                y = (z > 1.0f) ? z : 0.0f;
            }
#pragma unroll
            for (int j = 0; j < CH; ++j) b0[j] = b1[j];
#pragma unroll
            for (int j = 0; j < CH; ++j) b1[j] = b2[j];
        }
        out[(size_t)b * H + h] = y;
        return;
    }

    const int sub = bid & 7;
    const bool is_fp32 = sub < 2;
    int sig_idx;                                // (b*4 + tb) to signal

    if (is_fp32) {
        // ---------------- fp32 SGEMM (f32x2 + cp.async), h0 in [0,256) -----
        const int q  = (bid >> 3) * 2 + sub;            // 0..511
        const int hb = q & 1;
        const int r  = q >> 1;
        const int tb = r & 3;
        const int b  = r >> 2;
        const int t0 = tb * BM;
        const int h0 = hb * BN;
        sig_idx = b * 4 + tb;

        const uint32_t sb = s2u(smem);
        const float* Ab = x + (size_t)b * I * T + t0;
        const float* Bb = W + h0;

        const int rf = tid >> 5;
        const int cf = tid & 31;

        auto load_stage = [&](int kt) {
            const uint32_t sA = sb + (kt & 3) * F_STAGE;
            const uint32_t sB = sA + F_TILE;
            const float* Ap = Ab + (size_t)kt * FK * T;
            const float* Bp = Bb + (size_t)kt * FK * H;
            cp16(sA + rf * 512 + cf * 16,       Ap + (size_t)rf * T + cf * 4);
            cp16(sA + (rf + 8) * 512 + cf * 16, Ap + (size_t)(rf + 8) * T + cf * 4);
            cp16(sB + rf * 512 + cf * 16,       Bp + (size_t)rf * H + cf * 4);
            cp16(sB + (rf + 8) * 512 + cf * 16, Bp + (size_t)(rf + 8) * H + cf * 4);
        };

        load_stage(0); cp_commit();
        load_stage(1); cp_commit();
        load_stage(2); cp_commit();

        const int tx  = tid & 15;
        const int ty  = tid >> 4;
        const int tm0 = ty * FTM;
        const int tn0 = tx * FTN;

        uint64_t acc2[FTM][FTN / 2];
#pragma unroll
        for (int i = 0; i < FTM; ++i)
#pragma unroll
            for (int j = 0; j < FTN / 2; ++j) acc2[i][j] = 0ull;

        constexpr int KT = I / FK;                      // 32
        for (int kt = 0; kt < KT; ++kt) {
            cp_wait<2>();
            __syncthreads();
            if (kt + 3 < KT) load_stage(kt + 3);
            cp_commit();

            const float* As = (const float*)(smem + (kt & 3) * F_STAGE);
            const float* Bs = (const float*)(smem + (kt & 3) * F_STAGE + F_TILE);
#pragma unroll
            for (int kk = 0; kk < FK; ++kk) {
                float a[FTM];
                uint64_t bb2[FTN / 2];
                *(float4*)&a[0] = *(const float4*)&As[kk * BM + tm0];
                *(float4*)&a[4] = *(const float4*)&As[kk * BM + tm0 + 4];
                *(ulonglong2*)&bb2[0] = *(const ulonglong2*)&Bs[kk * BN + tn0];
                *(ulonglong2*)&bb2[2] = *(const ulonglong2*)&Bs[kk * BN + tn0 + 4];
#pragma unroll
                for (int i = 0; i < FTM; ++i) {
                    const uint64_t aa = pack2(a[i]);
#pragma unroll
                    for (int j = 0; j < FTN / 2; ++j)
                        fma2(acc2[i][j], aa, bb2[j]);
                }
            }
        }

#pragma unroll
        for (int i = 0; i < FTM; ++i) {
            const int t = t0 + tm0 + i;
            float v[FTN];
#pragma unroll
            for (int j = 0; j < FTN / 2; ++j)
                unpack2(acc2[i][j], v[2 * j], v[2 * j + 1]);
            float* o = g_proj + ((size_t)b * T + t) * H + h0 + tn0;
            *(float4*)(o)     = make_float4(v[0], v[1], v[2], v[3]);
            *(float4*)(o + 4) = make_float4(v[4], v[5], v[6], v[7]);
        }
    } else {
        // -------- fp16 2-product MMA (A-dedup), h0 in [256,1024) --------
        const int q  = (bid >> 3) * 6 + (sub - 2);      // 0..1535
        const int hb = q % 6;
        const int r  = q / 6;
        const int tb = r & 3;
        const int b  = r >> 2;
        const int t0 = tb * BM;
        const int h0 = 256 + hb * BN;
        sig_idx = b * 4 + tb;

        const uint32_t sb = s2u(smem);
        const int warp = tid >> 5;
        const int lane = tid & 31;
        const int wm = warp & 1;
        const int wn = warp >> 1;

        const int r0 = tid >> 1;
        const int c0 = (tid * 2) & 3;
        const int c1 = c0 + 1;

        const __half* Abase = g_Ax + ((size_t)(b * T + t0)) * I;
        const __half* Bhb = g_Wh + ((size_t)h0) * I;
        const __half* Blb = g_Wl + ((size_t)h0) * I;

        auto load_stage = [&](int kc) {
            const size_t i0 = (size_t)kc * KC;
            const uint32_t sA  = sb + (kc % STAGES) * STAGE_BYTES;
            const uint32_t sBh = sA + TILE_BYTES;
            const uint32_t sBl = sBh + TILE_BYTES;
            const __half* Ap  = Abase + i0;
            const __half* Bhp = Bhb + i0;
            const __half* Blp = Blb + i0;
            cp16(sA  + r0 * ROWB + c0 * 16, Ap  + (size_t)r0 * I + c0 * 8);
            cp16(sA  + r0 * ROWB + c1 * 16, Ap  + (size_t)r0 * I + c1 * 8);
            cp16(sBh + r0 * ROWB + c0 * 16, Bhp + (size_t)r0 * I + c0 * 8);
            cp16(sBh + r0 * ROWB + c1 * 16, Bhp + (size_t)r0 * I + c1 * 8);
            cp16(sBl + r0 * ROWB + c0 * 16, Blp + (size_t)r0 * I + c0 * 8);
            cp16(sBl + r0 * ROWB + c1 * 16, Blp + (size_t)r0 * I + c1 * 8);
        };

        load_stage(0); cp_commit();
        load_stage(1); cp_commit();

        float acc[4][4][4];
#pragma unroll
        for (int mt = 0; mt < 4; ++mt)
#pragma unroll
            for (int nj = 0; nj < 4; ++nj)
#pragma unroll
                for (int rr = 0; rr < 4; ++rr) acc[mt][nj][rr] = 0.0f;

        const int a_row = (lane & 15);
        const int a_kh  = (lane >> 4) * 8;
        const int b_row = (lane & 7) + ((lane >> 4) << 3);
        const int b_kh  = ((lane >> 3) & 1) * 8;

        for (int s = 0; s < NSTG; ++s) {
            cp_wait<STAGES - 2>();
            __syncthreads();
            if (s + STAGES - 1 < NSTG) load_stage(s + STAGES - 1);
            cp_commit();

            const uint32_t sA  = sb + (s % STAGES) * STAGE_BYTES;
            const uint32_t sBh = sA + TILE_BYTES;
            const uint32_t sBl = sBh + TILE_BYTES;

#pragma unroll
            for (int kk = 0; kk < KC; kk += 16) {
                uint32_t a[4][4], bb[2][4];
#pragma unroll
                for (int mt = 0; mt < 4; ++mt) {
                    const int m = wm * 64 + mt * 16 + a_row;
                    ldm_x4(a[mt][0], a[mt][1], a[mt][2], a[mt][3],
                           sA + m * ROWB + (kk + a_kh) * 2);
                }
#pragma unroll
                for (int nt = 0; nt < 2; ++nt) {
                    const int n = wn * 32 + nt * 16 + b_row;
                    ldm_x4(bb[nt][0], bb[nt][1], bb[nt][2], bb[nt][3],
                           sBh + n * ROWB + (kk + b_kh) * 2);
                }
#pragma unroll
                for (int mt = 0; mt < 4; ++mt)
#pragma unroll
                    for (int nj = 0; nj < 4; ++nj) {
                        const int nt = nj >> 1;
                        const int hh = (nj & 1) * 2;
                        mma16816(acc[mt][nj], a[mt], bb[nt][hh], bb[nt][hh + 1]);
                    }
#pragma unroll
                for (int nt = 0; nt < 2; ++nt) {
                    const int n = wn * 32 + nt * 16 + b_row;
                    ldm_x4(bb[nt][0], bb[nt][1], bb[nt][2], bb[nt][3],
                           sBl + n * ROWB + (kk + b_kh) * 2);
                }
#pragma unroll
                for (int mt = 0; mt < 4; ++mt)
#pragma unroll
                    for (int nj = 0; nj < 4; ++nj) {
                        const int nt = nj >> 1;
                        const int hh = (nj & 1) * 2;
                        mma16816(acc[mt][nj], a[mt], bb[nt][hh], bb[nt][hh + 1]);
                    }
            }
        }

#pragma unroll
        for (int mt = 0; mt < 4; ++mt) {
            const int tg = t0 + wm * 64 + mt * 16 + (lane >> 2);
            const float cc0 = g_csum[(size_t)b * T + tg];
            const float cc1 = g_csum[(size_t)b * T + tg + 8];
#pragma unroll
            for (int nj = 0; nj < 4; ++nj) {
                const int h = h0 + wn * 32 + nj * 8 + (lane & 3) * 2;
                float* o0 = g_proj + ((size_t)b * T + tg) * H + h;
                float* o1 = g_proj + ((size_t)b * T + tg + 8) * H + h;
                *(float2*)o0 = make_float2(acc[mt][nj][0] + cc0, acc[mt][nj][1] + cc0);
                *(float2*)o1 = make_float2(acc[mt][nj][2] + cc1, acc[mt][nj][3] + cc1);
            }
        }
    }

    // Tile completion signal: per-(b,tb).
    __syncthreads();
    if (tid == 0) {
        __threadfence();
        atomicAdd(&g_cnt[sig_idx], 1);
    }
}

// ---------------------------------------------------------------------------
extern "C" void kernel_launch(void* const* d_in, const int* in_sizes, int n_in,
                              void* d_out, int out_size) {
    const float* x    = (const float*)d_in[0];  // (B, I, T)
    const float* W    = (const float*)d_in[1];  // (I, H)
    const float* bias = (const float*)d_in[2];  // (1, H)
    float* out        = (float*)d_out;          // (B, H)

    cudaFuncSetAttribute(gemm_hybrid, cudaFuncAttributeMaxDynamicSharedMemorySize,
                         SMEM_DYN);

    conv_x<<<dim3(T / 32, I / 64, B), dim3(32, 8)>>>(x);
    conv_w_reduce<<<512 + (B * T) / 256, 256>>>(W);
    gemm_hybrid<<<2048 + 256, 256, SMEM_DYN>>>(x, W, bias, out);
}